// round 3
// baseline (speedup 1.0000x reference)
#include <cuda_runtime.h>

#define NB   2
#define NP   8192
#define KNN  10
#define K1   11          // top-(K+1), smallest entry is "self"
#define BLK  32
#define NBLK ((NB * NP) / BLK)   // 512 blocks

// Scratch (no allocations allowed): packed (x,y,z,|p|^2) for point1, block partial sums.
__device__ float4 g_pts[NB * NP];
__device__ float  g_part[NBLK];

// ---------------------------------------------------------------------------
// Pack point1 into float4 with precomputed squared norm.
// ---------------------------------------------------------------------------
__global__ void prep_kernel(const float* __restrict__ p1) {
    int i = blockIdx.x * blockDim.x + threadIdx.x;
    if (i < NB * NP) {
        float x = p1[3 * i + 0];
        float y = p1[3 * i + 1];
        float z = p1[3 * i + 2];
        g_pts[i] = make_float4(x, y, z, x * x + y * y + z * z);
    }
}

// ---------------------------------------------------------------------------
// One query point per THREAD. All 32 lanes of a warp stream the same candidate
// sequence (uniform-address LDG.128, L1-resident), so the rare top-K insert is
// the only divergence. Maintains a sorted ascending (metric, idx)[11] list in
// registers. Metric is d2' = |p|^2 - 2*q.p = |p-q|^2 - |q|^2 (constant shift
// of true d2 per query -> identical ordering, one less FADD per candidate).
// Entry 0 is the strict minimum (self) and is dropped — same semantics as
// reference's idx[:, :, 1:].
// ---------------------------------------------------------------------------
__global__ void __launch_bounds__(BLK) knn_loss_kernel(const float* __restrict__ p2) {
    const int q  = blockIdx.x * BLK + threadIdx.x;   // 0 .. 16383
    const int b  = q >> 13;                          // batch
    const int qi = q & (NP - 1);                     // point index in batch
    const float4* __restrict__ pts = g_pts + b * NP;

    const float4 me = pts[qi];
    const float  cx = -2.0f * me.x;
    const float  cy = -2.0f * me.y;
    const float  cz = -2.0f * me.z;

    float dk[K1];
    int   id[K1];
#pragma unroll
    for (int t = 0; t < K1; ++t) { dk[t] = 3.4e38f; id[t] = 0; }

#pragma unroll 8
    for (int j = 0; j < NP; ++j) {
        float4 p  = __ldg(&pts[j]);
        // metric = |p|^2 - 2*dot(q, p)  (d2 shifted by -|q|^2)
        float d2 = fmaf(p.x, cx, fmaf(p.y, cy, fmaf(p.z, cz, p.w)));
        if (d2 < dk[K1 - 1]) {
            dk[K1 - 1] = d2;
            id[K1 - 1] = j;
#pragma unroll
            for (int t = K1 - 1; t > 0; --t) {
                if (dk[t] < dk[t - 1]) {
                    float td = dk[t]; dk[t] = dk[t - 1]; dk[t - 1] = td;
                    int   ti = id[t]; id[t] = id[t - 1]; id[t - 1] = ti;
                }
            }
        }
    }

    // Gather the 10 true neighbors (entries 1..10) from both clouds.
    float s1x = 0.f, s1y = 0.f, s1z = 0.f;
    float s2x = 0.f, s2y = 0.f, s2z = 0.f;
#pragma unroll
    for (int t = 1; t < K1; ++t) {
        int j = id[t];
        float4 p = pts[j];
        s1x += p.x; s1y += p.y; s1z += p.z;
        const float* r = p2 + (size_t)(b * NP + j) * 3;
        s2x += r[0]; s2y += r[1]; s2z += r[2];
    }
    const float* mq2 = p2 + (size_t)(b * NP + qi) * 3;
    const float  inv = 1.0f / (float)KNN;

    // |lap1 - lap2| summed over the 3 coordinates.
    float v = fabsf((s1x * inv - me.x) - (s2x * inv - mq2[0]))
            + fabsf((s1y * inv - me.y) - (s2y * inv - mq2[1]))
            + fabsf((s1z * inv - me.z) - (s2z * inv - mq2[2]));

    // Deterministic fixed-order block reduction (single warp: shfl-free smem tree).
    __shared__ float red[BLK];
    red[threadIdx.x] = v;
    __syncthreads();
#pragma unroll
    for (int s = BLK / 2; s > 0; s >>= 1) {
        if (threadIdx.x < s) red[threadIdx.x] += red[threadIdx.x + s];
        __syncthreads();
    }
    if (threadIdx.x == 0) g_part[blockIdx.x] = red[0];
}

// ---------------------------------------------------------------------------
// Final deterministic reduction of the 512 block partials -> mean.
// ---------------------------------------------------------------------------
__global__ void reduce_kernel(float* __restrict__ out) {
    __shared__ float red[256];
    float s = 0.0f;
    for (int i = threadIdx.x; i < NBLK; i += 256) s += g_part[i];
    red[threadIdx.x] = s;
    __syncthreads();
    for (int st = 128; st > 0; st >>= 1) {
        if (threadIdx.x < st) red[threadIdx.x] += red[threadIdx.x + st];
        __syncthreads();
    }
    if (threadIdx.x == 0) out[0] = red[0] / (float)(NB * NP * 3);
}

extern "C" void kernel_launch(void* const* d_in, const int* in_sizes, int n_in,
                              void* d_out, int out_size) {
    const float* p1 = (const float*)d_in[0];
    const float* p2 = (const float*)d_in[1];
    float* out = (float*)d_out;

    prep_kernel<<<(NB * NP + 255) / 256, 256>>>(p1);
    knn_loss_kernel<<<NBLK, BLK>>>(p2);
    reduce_kernel<<<1, 256>>>(out);
}

// round 4
// speedup vs baseline: 2.0201x; 2.0201x over previous
#include <cuda_runtime.h>

#define NB   2
#define NP   8192
#define KNN  10
#define K1   11            // top-(K+1); min entry is "self", dropped
#define HALF (NP / 2)      // each thread scans one half of the cloud
#define GRP  8
#define NGRP (HALF / GRP)  // 512 groups per half-scan
#define BLK  128
#define NQ   (NB * NP)             // 16384 queries
#define NTH  (NQ * 2)              // 2 threads per query
#define NBLK (NTH / BLK)           // 256 blocks

// Scratch (no allocations allowed).
__device__ float4 g_pts[NB * NP];
__device__ float  g_part[NBLK];

// ---------------------------------------------------------------------------
__global__ void prep_kernel(const float* __restrict__ p1) {
    int i = blockIdx.x * blockDim.x + threadIdx.x;
    if (i < NB * NP) {
        float x = p1[3 * i + 0];
        float y = p1[3 * i + 1];
        float z = p1[3 * i + 2];
        g_pts[i] = make_float4(x, y, z, x * x + y * y + z * z);
    }
}

// Branch-free sorted insert: replace current max (slot K1-1), then a fully
// predicated compare-swap bubble pass (no nested if -> no BSSY/BSYNC).
__device__ __forceinline__ void topk_insert(float dv, int jj, float* dk, int* id) {
    dk[K1 - 1] = dv;
    id[K1 - 1] = jj;
#pragma unroll
    for (int t = K1 - 1; t > 0; --t) {
        bool sw  = dk[t] < dk[t - 1];
        float lo = sw ? dk[t] : dk[t - 1];
        float hi = sw ? dk[t - 1] : dk[t];
        int  ilo = sw ? id[t] : id[t - 1];
        int  ihi = sw ? id[t - 1] : id[t];
        dk[t - 1] = lo; dk[t] = hi;
        id[t - 1] = ilo; id[t] = ihi;
    }
}

// ---------------------------------------------------------------------------
// 2 threads per query. Within a warp: lanes 0..15 handle 16 queries scanning
// candidate half 0; lanes 16..31 handle the SAME 16 queries scanning half 1.
// Each half-warp streams one uniform candidate address sequence (2 sectors per
// LDG.128 for the warp). Per group of 8 candidates: branchless distance + min
// tree, one rare branch into the insert path. Metric d2' = |p|^2 - 2 q.p
// (order-identical to true d2; strict min at self).
// ---------------------------------------------------------------------------
__global__ void __launch_bounds__(BLK) knn_loss_kernel(const float* __restrict__ p2) {
    const int tid  = blockIdx.x * BLK + threadIdx.x;
    const int w    = tid >> 5;                 // global warp id (16 queries each)
    const int lane = threadIdx.x & 31;
    const int half = lane >> 4;                // 0 or 1
    const int q    = w * 16 + (lane & 15);     // 0 .. 16383
    const int b    = q >> 13;
    const int qi   = q & (NP - 1);

    const float4* __restrict__ pts = g_pts + b * NP;
    const float4 me = pts[qi];
    const float cx = -2.0f * me.x;
    const float cy = -2.0f * me.y;
    const float cz = -2.0f * me.z;

    const int jbase = half * HALF;
    const float4* __restrict__ ph = pts + jbase;

    float dk[K1];
    int   id[K1];
#pragma unroll
    for (int t = 0; t < K1; ++t) { dk[t] = 3.4e38f; id[t] = 0; }

    for (int g = 0; g < NGRP; ++g) {
        const float4* pp = ph + g * GRP;
        float4 P0 = __ldg(pp + 0), P1 = __ldg(pp + 1);
        float4 P2 = __ldg(pp + 2), P3 = __ldg(pp + 3);
        float4 P4 = __ldg(pp + 4), P5 = __ldg(pp + 5);
        float4 P6 = __ldg(pp + 6), P7 = __ldg(pp + 7);

        float d0 = fmaf(P0.x, cx, fmaf(P0.y, cy, fmaf(P0.z, cz, P0.w)));
        float d1 = fmaf(P1.x, cx, fmaf(P1.y, cy, fmaf(P1.z, cz, P1.w)));
        float d2 = fmaf(P2.x, cx, fmaf(P2.y, cy, fmaf(P2.z, cz, P2.w)));
        float d3 = fmaf(P3.x, cx, fmaf(P3.y, cy, fmaf(P3.z, cz, P3.w)));
        float d4 = fmaf(P4.x, cx, fmaf(P4.y, cy, fmaf(P4.z, cz, P4.w)));
        float d5 = fmaf(P5.x, cx, fmaf(P5.y, cy, fmaf(P5.z, cz, P5.w)));
        float d6 = fmaf(P6.x, cx, fmaf(P6.y, cy, fmaf(P6.z, cz, P6.w)));
        float d7 = fmaf(P7.x, cx, fmaf(P7.y, cy, fmaf(P7.z, cz, P7.w)));

        float m = fminf(fminf(fminf(d0, d1), fminf(d2, d3)),
                        fminf(fminf(d4, d5), fminf(d6, d7)));
        if (m < dk[K1 - 1]) {
            const int j0 = jbase + g * GRP;
            if (d0 < dk[K1 - 1]) topk_insert(d0, j0 + 0, dk, id);
            if (d1 < dk[K1 - 1]) topk_insert(d1, j0 + 1, dk, id);
            if (d2 < dk[K1 - 1]) topk_insert(d2, j0 + 2, dk, id);
            if (d3 < dk[K1 - 1]) topk_insert(d3, j0 + 3, dk, id);
            if (d4 < dk[K1 - 1]) topk_insert(d4, j0 + 4, dk, id);
            if (d5 < dk[K1 - 1]) topk_insert(d5, j0 + 5, dk, id);
            if (d6 < dk[K1 - 1]) topk_insert(d6, j0 + 6, dk, id);
            if (d7 < dk[K1 - 1]) topk_insert(d7, j0 + 7, dk, id);
        }
    }

    // Exchange half-lists through shared memory (dynamic indices -> LDS).
    __shared__ float sd[BLK / 32][32][K1];
    __shared__ int   si[BLK / 32][32][K1];
    const int wl = threadIdx.x >> 5;
#pragma unroll
    for (int t = 0; t < K1; ++t) { sd[wl][lane][t] = dk[t]; si[wl][lane][t] = id[t]; }
    __syncwarp();

    float v = 0.0f;
    if (lane < 16) {
        const float* dA = sd[wl][lane];       const int* iA = si[wl][lane];
        const float* dB = sd[wl][lane + 16];  const int* iB = si[wl][lane + 16];
        // Two-pointer merge: pick 11 smallest of the union. Ties -> list A
        // (half 0 = smaller indices), matching top_k ascending-index tie order.
        // Pick 0 is the global min = self; picks 1..10 are the true neighbors.
        int i1 = 0, i2 = 0;
        float s1x = 0.f, s1y = 0.f, s1z = 0.f;
        float s2x = 0.f, s2y = 0.f, s2z = 0.f;
#pragma unroll
        for (int t = 0; t < K1; ++t) {
            float a = dA[i1], bb = dB[i2];
            bool ta = (a <= bb);
            int idx = ta ? iA[i1] : iB[i2];
            if (ta) ++i1; else ++i2;
            if (t > 0) {
                float4 pn = pts[idx];
                s1x += pn.x; s1y += pn.y; s1z += pn.z;
                const float* r = p2 + (size_t)(b * NP + idx) * 3;
                s2x += r[0]; s2y += r[1]; s2z += r[2];
            }
        }
        const float* mq2 = p2 + (size_t)(b * NP + qi) * 3;
        const float inv = 1.0f / (float)KNN;
        v = fabsf((s1x * inv - me.x) - (s2x * inv - mq2[0]))
          + fabsf((s1y * inv - me.y) - (s2y * inv - mq2[1]))
          + fabsf((s1z * inv - me.z) - (s2z * inv - mq2[2]));
    }

    // Deterministic fixed-order block reduction.
    __shared__ float red[BLK];
    red[threadIdx.x] = v;
    __syncthreads();
#pragma unroll
    for (int s = BLK / 2; s > 0; s >>= 1) {
        if (threadIdx.x < s) red[threadIdx.x] += red[threadIdx.x + s];
        __syncthreads();
    }
    if (threadIdx.x == 0) g_part[blockIdx.x] = red[0];
}

// ---------------------------------------------------------------------------
__global__ void reduce_kernel(float* __restrict__ out) {
    __shared__ float red[256];
    float s = 0.0f;
    for (int i = threadIdx.x; i < NBLK; i += 256) s += g_part[i];
    red[threadIdx.x] = s;
    __syncthreads();
    for (int st = 128; st > 0; st >>= 1) {
        if (threadIdx.x < st) red[threadIdx.x] += red[threadIdx.x + st];
        __syncthreads();
    }
    if (threadIdx.x == 0) out[0] = red[0] / (float)(NB * NP * 3);
}

extern "C" void kernel_launch(void* const* d_in, const int* in_sizes, int n_in,
                              void* d_out, int out_size) {
    const float* p1 = (const float*)d_in[0];
    const float* p2 = (const float*)d_in[1];
    float* out = (float*)d_out;

    prep_kernel<<<(NB * NP + 255) / 256, 256>>>(p1);
    knn_loss_kernel<<<NBLK, BLK>>>(p2);
    reduce_kernel<<<1, 256>>>(out);
}

// round 6
// speedup vs baseline: 3.5333x; 1.7490x over previous
#include <cuda_runtime.h>

#define NB   2
#define NP   8192
#define KNN  10
#define K1   11           // top-(K+1); min entry is "self", dropped
#define WPB  8            // warps per block
#define BLK  (WPB * 32)
#define NQ   (NB * NP)            // 16384 queries = 16384 warps
#define NBLK (NQ / WPB)           // 2048 blocks

// Scratch (no allocations allowed).
__device__ float4 g_pts[NB * NP];
__device__ float  g_part[NBLK];

// ---------------------------------------------------------------------------
__global__ void prep_kernel(const float* __restrict__ p1) {
    int i = blockIdx.x * blockDim.x + threadIdx.x;
    if (i < NB * NP) {
        float x = p1[3 * i + 0];
        float y = p1[3 * i + 1];
        float z = p1[3 * i + 2];
        g_pts[i] = make_float4(x, y, z, x * x + y * y + z * z);
    }
}

// Uniform (all-lane replicated) sorted insert of (key, idx); keys are uint32
// bit-images of nonnegative floats so unsigned compare == float compare.
// Strict < keeps earlier-inserted (lower index) entries ahead on exact ties,
// matching lax.top_k's ascending-index tie order.
__device__ __forceinline__ void topk_insert(unsigned k, int j,
                                            unsigned* dk, int* id) {
    dk[K1 - 1] = k;
    id[K1 - 1] = j;
#pragma unroll
    for (int t = K1 - 1; t > 0; --t) {
        bool sw = dk[t] < dk[t - 1];
        unsigned a = sw ? dk[t] : dk[t - 1];
        unsigned c = sw ? dk[t - 1] : dk[t];
        int ia = sw ? id[t] : id[t - 1];
        int ic = sw ? id[t - 1] : id[t];
        dk[t - 1] = a; dk[t] = c;
        id[t - 1] = ia; id[t] = ic;
    }
}

// ---------------------------------------------------------------------------
// ONE QUERY PER WARP. Lanes stream coalesced candidates (lane l takes
// j = 128*it + 32*u + l). Distance d2 = |q|^2 + |p|^2 - 2 q.p, clamped to 0
// (only self can go negative via cancellation); its float bits form a uint32
// key with identical ordering. A single REDUX.UMIN screens 128 candidates
// against the warp-shared list max; inserts happen only on actual top-K
// events (~73/query), executed uniformly by all lanes on a replicated list.
// ---------------------------------------------------------------------------
__global__ void __launch_bounds__(BLK) knn_loss_kernel(const float* __restrict__ p2) {
    const int w    = threadIdx.x >> 5;
    const int lane = threadIdx.x & 31;
    const int q    = blockIdx.x * WPB + w;      // 0 .. 16383
    const int b    = q >> 13;
    const int qi   = q & (NP - 1);

    const float4* __restrict__ pts = g_pts + b * NP;
    const float4 me = pts[qi];
    const float cx = -2.0f * me.x;
    const float cy = -2.0f * me.y;
    const float cz = -2.0f * me.z;
    const float base = me.w;

    unsigned dk[K1];
    int      id[K1];
#pragma unroll
    for (int t = 0; t < K1; ++t) { dk[t] = 0xFFFFFFFFu; id[t] = 0; }

    for (int it = 0; it < NP / 128; ++it) {
        const int j0 = it * 128;
        float4 a0 = __ldg(&pts[j0 +  0 + lane]);
        float4 a1 = __ldg(&pts[j0 + 32 + lane]);
        float4 a2 = __ldg(&pts[j0 + 64 + lane]);
        float4 a3 = __ldg(&pts[j0 + 96 + lane]);

        float d0 = fmaf(a0.x, cx, fmaf(a0.y, cy, fmaf(a0.z, cz, base + a0.w)));
        float d1 = fmaf(a1.x, cx, fmaf(a1.y, cy, fmaf(a1.z, cz, base + a1.w)));
        float d2 = fmaf(a2.x, cx, fmaf(a2.y, cy, fmaf(a2.z, cz, base + a2.w)));
        float d3 = fmaf(a3.x, cx, fmaf(a3.y, cy, fmaf(a3.z, cz, base + a3.w)));

        unsigned key[4];
        key[0] = __float_as_uint(fmaxf(d0, 0.0f));
        key[1] = __float_as_uint(fmaxf(d1, 0.0f));
        key[2] = __float_as_uint(fmaxf(d2, 0.0f));
        key[3] = __float_as_uint(fmaxf(d3, 0.0f));

        unsigned m = min(min(key[0], key[1]), min(key[2], key[3]));
        unsigned wm = __reduce_min_sync(0xFFFFFFFFu, m);
        if (wm < dk[K1 - 1]) {
#pragma unroll
            for (int u = 0; u < 4; ++u) {
                while (true) {
                    unsigned wk = __reduce_min_sync(0xFFFFFFFFu, key[u]);
                    if (wk >= dk[K1 - 1]) break;          // uniform exit
                    unsigned bal = __ballot_sync(0xFFFFFFFFu, key[u] == wk);
                    int src = __ffs(bal) - 1;             // lowest lane = lowest idx
                    topk_insert(wk, j0 + u * 32 + src, dk, id);
                    if (lane == src) key[u] = 0xFFFFFFFFu;
                }
            }
        }
    }

    // Entry 0 is self (d2 ~ 0, strict min). Lanes 1..10 gather one neighbor
    // each; indices staged through smem to avoid dynamic register indexing.
    __shared__ int sid[WPB][K1 + 1];
    if (lane == 0) {
#pragma unroll
        for (int t = 0; t < K1; ++t) sid[w][t] = id[t];
    }
    __syncwarp();

    float sx = 0.f, sy = 0.f, sz = 0.f;
    float rx = 0.f, ry = 0.f, rz = 0.f;
    if (lane >= 1 && lane < K1) {
        int jn = sid[w][lane];
        float4 pn = pts[jn];
        sx = pn.x; sy = pn.y; sz = pn.z;
        const float* r = p2 + (size_t)(b * NP + jn) * 3;
        rx = r[0]; ry = r[1]; rz = r[2];
    }
    // Fixed-order shfl tree over lanes 0..15 (lanes 0 and 11..15 contribute 0).
#pragma unroll
    for (int off = 8; off > 0; off >>= 1) {
        sx += __shfl_down_sync(0xFFFFFFFFu, sx, off, 16);
        sy += __shfl_down_sync(0xFFFFFFFFu, sy, off, 16);
        sz += __shfl_down_sync(0xFFFFFFFFu, sz, off, 16);
        rx += __shfl_down_sync(0xFFFFFFFFu, rx, off, 16);
        ry += __shfl_down_sync(0xFFFFFFFFu, ry, off, 16);
        rz += __shfl_down_sync(0xFFFFFFFFu, rz, off, 16);
    }

    __shared__ float sred[WPB];
    if (lane == 0) {
        const float* mq2 = p2 + (size_t)(b * NP + qi) * 3;
        const float inv = 1.0f / (float)KNN;
        float v = fabsf((sx * inv - me.x) - (rx * inv - mq2[0]))
                + fabsf((sy * inv - me.y) - (ry * inv - mq2[1]))
                + fabsf((sz * inv - me.z) - (rz * inv - mq2[2]));
        sred[w] = v;
    }
    __syncthreads();
    if (threadIdx.x == 0) {
        float s = 0.0f;
#pragma unroll
        for (int i = 0; i < WPB; ++i) s += sred[i];
        g_part[blockIdx.x] = s;
    }
}

// ---------------------------------------------------------------------------
__global__ void reduce_kernel(float* __restrict__ out) {
    __shared__ float red[256];
    float s = 0.0f;
    for (int i = threadIdx.x; i < NBLK; i += 256) s += g_part[i];
    red[threadIdx.x] = s;
    __syncthreads();
    for (int st = 128; st > 0; st >>= 1) {
        if (threadIdx.x < st) red[threadIdx.x] += red[threadIdx.x + st];
        __syncthreads();
    }
    if (threadIdx.x == 0) out[0] = red[0] / (float)(NB * NP * 3);
}

extern "C" void kernel_launch(void* const* d_in, const int* in_sizes, int n_in,
                              void* d_out, int out_size) {
    const float* p1 = (const float*)d_in[0];
    const float* p2 = (const float*)d_in[1];
    float* out = (float*)d_out;

    prep_kernel<<<(NB * NP + 255) / 256, 256>>>(p1);
    knn_loss_kernel<<<NBLK, BLK>>>(p2);
    reduce_kernel<<<1, 256>>>(out);
}

// round 7
// speedup vs baseline: 6.1148x; 1.7306x over previous
#include <cuda_runtime.h>

#define NB   2
#define NP   8192
#define KNN  10
#define K1   11           // top-(K+1); min entry is "self", dropped
#define WPB  8            // warps per block
#define BLK  (WPB * 32)
#define NQ   (NB * NP)            // 16384 queries = 16384 warps
#define NBLK (NQ / WPB)           // 2048 blocks
#define FULL 0xFFFFFFFFu

// Scratch (no allocations allowed).
__device__ float4 g_pts[NB * NP];
__device__ float  g_part[NBLK];

// ---------------------------------------------------------------------------
__global__ void prep_kernel(const float* __restrict__ p1) {
    int i = blockIdx.x * blockDim.x + threadIdx.x;
    if (i < NB * NP) {
        float x = p1[3 * i + 0];
        float y = p1[3 * i + 1];
        float z = p1[3 * i + 2];
        g_pts[i] = make_float4(x, y, z, x * x + y * y + z * z);
    }
}

// ---------------------------------------------------------------------------
// ONE QUERY PER WARP, lane-DISTRIBUTED top-11 list: lane t (t<=10) holds the
// t-th smallest (key, idx) seen so far; keys are uint32 bit-images of
// nonnegative floats (unsigned order == float order). Insert is O(1):
//   pos  = popc(ballot(ekey <= wk) & 0x7FF)   // after-equals => index order
//   lanes > pos shift up by one via shfl; lane pos takes the new pair.
// Elections pick the lowest lane (= lowest global index) among equal keys and
// scan order is ascending index, so tie semantics match lax.top_k exactly.
// Entry at lane 0 is self (clamped d2 = 0, strict min) and is dropped.
// ---------------------------------------------------------------------------
__global__ void __launch_bounds__(BLK) knn_loss_kernel(const float* __restrict__ p2) {
    const int w    = threadIdx.x >> 5;
    const int lane = threadIdx.x & 31;
    const int q    = blockIdx.x * WPB + w;      // 0 .. 16383
    const int b    = q >> 13;
    const int qi   = q & (NP - 1);

    const float4* __restrict__ pts = g_pts + b * NP;
    const float4 me = pts[qi];
    const float cx = -2.0f * me.x;
    const float cy = -2.0f * me.y;
    const float cz = -2.0f * me.z;
    const float base = me.w;

    unsigned ekey = FULL;   // list entry key (lanes 0..10 meaningful)
    int      eidx = 0;      // list entry index
    unsigned dkmax = FULL;  // current 11th-smallest key (entry at lane 10)

    for (int it = 0; it < NP / 128; ++it) {
        const int j0 = it * 128;
        float4 a0 = __ldg(&pts[j0 +  0 + lane]);
        float4 a1 = __ldg(&pts[j0 + 32 + lane]);
        float4 a2 = __ldg(&pts[j0 + 64 + lane]);
        float4 a3 = __ldg(&pts[j0 + 96 + lane]);

        float d0 = fmaf(a0.x, cx, fmaf(a0.y, cy, fmaf(a0.z, cz, base + a0.w)));
        float d1 = fmaf(a1.x, cx, fmaf(a1.y, cy, fmaf(a1.z, cz, base + a1.w)));
        float d2 = fmaf(a2.x, cx, fmaf(a2.y, cy, fmaf(a2.z, cz, base + a2.w)));
        float d3 = fmaf(a3.x, cx, fmaf(a3.y, cy, fmaf(a3.z, cz, base + a3.w)));

        unsigned key[4];
        key[0] = __float_as_uint(fmaxf(d0, 0.0f));
        key[1] = __float_as_uint(fmaxf(d1, 0.0f));
        key[2] = __float_as_uint(fmaxf(d2, 0.0f));
        key[3] = __float_as_uint(fmaxf(d3, 0.0f));

        unsigned m = min(min(key[0], key[1]), min(key[2], key[3]));
        unsigned wm = __reduce_min_sync(FULL, m);
        if (wm < dkmax) {
#pragma unroll
            for (int u = 0; u < 4; ++u) {
                while (true) {
                    unsigned wk = __reduce_min_sync(FULL, key[u]);
                    if (wk >= dkmax) break;               // uniform exit
                    unsigned bal = __ballot_sync(FULL, key[u] == wk);
                    int src = __ffs(bal) - 1;             // lowest lane = lowest idx
                    int ji  = j0 + u * 32 + src;          // uniform (src uniform)
                    // O(1) distributed insert
                    unsigned keep = __ballot_sync(FULL, ekey <= wk);
                    int pos = __popc(keep & 0x7FFu);      // insertion slot
                    unsigned pk = __shfl_up_sync(FULL, ekey, 1);
                    int      pi = __shfl_up_sync(FULL, eidx, 1);
                    bool take  = (lane == pos);
                    bool shift = (lane > pos) && (lane <= 10);
                    ekey = take ? wk : (shift ? pk : ekey);
                    eidx = take ? ji : (shift ? pi : eidx);
                    dkmax = __shfl_sync(FULL, ekey, 10);
                    if (lane == src) key[u] = FULL;       // consume elected key
                }
            }
        }
    }

    // Lane t (1..10) holds the t-th neighbor directly; lane 0 holds self.
    float sx = 0.f, sy = 0.f, sz = 0.f;
    float rx = 0.f, ry = 0.f, rz = 0.f;
    if (lane >= 1 && lane < K1) {
        float4 pn = pts[eidx];
        sx = pn.x; sy = pn.y; sz = pn.z;
        const float* r = p2 + (size_t)(b * NP + eidx) * 3;
        rx = __ldg(r + 0); ry = __ldg(r + 1); rz = __ldg(r + 2);
    }
    // Fixed-order shfl tree over lanes 0..15 (lanes 0 and 11..15 contribute 0).
#pragma unroll
    for (int off = 8; off > 0; off >>= 1) {
        sx += __shfl_down_sync(FULL, sx, off, 16);
        sy += __shfl_down_sync(FULL, sy, off, 16);
        sz += __shfl_down_sync(FULL, sz, off, 16);
        rx += __shfl_down_sync(FULL, rx, off, 16);
        ry += __shfl_down_sync(FULL, ry, off, 16);
        rz += __shfl_down_sync(FULL, rz, off, 16);
    }

    __shared__ float sred[WPB];
    if (lane == 0) {
        const float* mq2 = p2 + (size_t)(b * NP + qi) * 3;
        const float inv = 1.0f / (float)KNN;
        float v = fabsf((sx * inv - me.x) - (rx * inv - mq2[0]))
                + fabsf((sy * inv - me.y) - (ry * inv - mq2[1]))
                + fabsf((sz * inv - me.z) - (rz * inv - mq2[2]));
        sred[w] = v;
    }
    __syncthreads();
    if (threadIdx.x == 0) {
        float s = 0.0f;
#pragma unroll
        for (int i = 0; i < WPB; ++i) s += sred[i];
        g_part[blockIdx.x] = s;
    }
}

// ---------------------------------------------------------------------------
__global__ void reduce_kernel(float* __restrict__ out) {
    __shared__ float red[256];
    float s = 0.0f;
    for (int i = threadIdx.x; i < NBLK; i += 256) s += g_part[i];
    red[threadIdx.x] = s;
    __syncthreads();
    for (int st = 128; st > 0; st >>= 1) {
        if (threadIdx.x < st) red[threadIdx.x] += red[threadIdx.x + st];
        __syncthreads();
    }
    if (threadIdx.x == 0) out[0] = red[0] / (float)(NB * NP * 3);
}

extern "C" void kernel_launch(void* const* d_in, const int* in_sizes, int n_in,
                              void* d_out, int out_size) {
    const float* p1 = (const float*)d_in[0];
    const float* p2 = (const float*)d_in[1];
    float* out = (float*)d_out;

    prep_kernel<<<(NB * NP + 255) / 256, 256>>>(p1);
    knn_loss_kernel<<<NBLK, BLK>>>(p2);
    reduce_kernel<<<1, 256>>>(out);
}